// round 1
// baseline (speedup 1.0000x reference)
#include <cuda_runtime.h>
#include <math.h>

// Problem constants
#define T_STEPS 1024
#define BATCH   16
#define HID     512
#define NBLK    128   // persistent recurrence grid
#define RS      36    // padded shared row stride (floats) for 32-wide interleaved tiles

typedef unsigned long long ull;

// ------------------------- static device scratch -------------------------
__device__ float g_gx[(size_t)BATCH * T_STEPS * 4 * HID];   // 134 MB: gate preactivations (input part)
__device__ float g_seq[(size_t)BATCH * T_STEPS * HID];      // 33.5 MB: layer-0 output sequence
__device__ float g_hT[2][HID / 2][32];                      // double-buffered h, k-pair interleaved: [p][n>>1][b*2+(n&1)]
__device__ unsigned g_arrive;
__device__ unsigned g_release;

// ------------------------- f32x2 helpers -------------------------
__device__ __forceinline__ ull ffma2(ull a, ull b, ull c) {
    ull d;
    asm("fma.rn.f32x2 %0, %1, %2, %3;" : "=l"(d) : "l"(a), "l"(b), "l"(c));
    return d;
}
__device__ __forceinline__ ull splat2(float a) {
    ull d;
    asm("mov.b64 %0, {%1, %1};" : "=l"(d) : "f"(a));
    return d;
}
__device__ __forceinline__ float2 unpack2(ull v) {
    float2 f;
    asm("mov.b64 {%0, %1}, %2;" : "=f"(f.x), "=f"(f.y) : "l"(v));
    return f;
}
__device__ __forceinline__ float sigm(float x) { return 1.0f / (1.0f + __expf(-x)); }

// ------------------------- init: reset barrier + transpose h0 -------------------------
__global__ void init_state(const float* __restrict__ h0) {
    int i = blockIdx.x * blockDim.x + threadIdx.x;
    if (i == 0) { g_arrive = 0u; g_release = 0u; }
    if (i < HID * BATCH) {
        int n = i >> 4, b = i & 15;
        g_hT[0][n >> 1][b * 2 + (n & 1)] = h0[b * HID + n];
    }
}

// ------------------------- big GEMM: gx = A @ W^T + bias -------------------------
// A: [M=16384][K=512] row-major, W: [N=2048][K=512] row-major, C = g_gx [M][N]
// 128x128 tile, 8x8 per thread, f32x2-packed along M (row pairs).
__global__ __launch_bounds__(256) void gemm_gates(const float* __restrict__ Aext, int useSeq,
                                                  const float* __restrict__ W,
                                                  const float* __restrict__ bias) {
    const float* A = useSeq ? g_seq : Aext;
    __shared__ float As[16][128];
    __shared__ float Bs[16][128];
    const int tid = threadIdx.x;
    const int tx = tid & 15, ty = tid >> 4;
    const int bn = blockIdx.x, bm = blockIdx.y;
    const float* Ab = A + (size_t)bm * 128 * 512;
    const float* Wb = W + (size_t)bn * 128 * 512;
    const int lr = tid >> 2;
    const int lc = (tid & 3) << 2;

    ull acc2[4][8];
#pragma unroll
    for (int i = 0; i < 4; i++)
#pragma unroll
        for (int j = 0; j < 8; j++) acc2[i][j] = 0ull;

    for (int k0 = 0; k0 < 512; k0 += 16) {
        float4 a0 = *(const float4*)(Ab + (size_t)lr * 512 + k0 + lc);
        float4 a1 = *(const float4*)(Ab + (size_t)(lr + 64) * 512 + k0 + lc);
        float4 w0 = *(const float4*)(Wb + (size_t)lr * 512 + k0 + lc);
        float4 w1 = *(const float4*)(Wb + (size_t)(lr + 64) * 512 + k0 + lc);
        __syncthreads();
        As[lc + 0][lr] = a0.x; As[lc + 1][lr] = a0.y; As[lc + 2][lr] = a0.z; As[lc + 3][lr] = a0.w;
        As[lc + 0][lr + 64] = a1.x; As[lc + 1][lr + 64] = a1.y; As[lc + 2][lr + 64] = a1.z; As[lc + 3][lr + 64] = a1.w;
        Bs[lc + 0][lr] = w0.x; Bs[lc + 1][lr] = w0.y; Bs[lc + 2][lr] = w0.z; Bs[lc + 3][lr] = w0.w;
        Bs[lc + 0][lr + 64] = w1.x; Bs[lc + 1][lr + 64] = w1.y; Bs[lc + 2][lr + 64] = w1.z; Bs[lc + 3][lr + 64] = w1.w;
        __syncthreads();
#pragma unroll
        for (int k = 0; k < 16; k++) {
            ulonglong2 av0 = *(const ulonglong2*)&As[k][ty * 8];
            ulonglong2 av1 = *(const ulonglong2*)&As[k][ty * 8 + 4];
            float4 bv0 = *(const float4*)&Bs[k][tx * 8];
            float4 bv1 = *(const float4*)&Bs[k][tx * 8 + 4];
            ull ap[4] = {av0.x, av0.y, av1.x, av1.y};
            ull bp[8] = {splat2(bv0.x), splat2(bv0.y), splat2(bv0.z), splat2(bv0.w),
                         splat2(bv1.x), splat2(bv1.y), splat2(bv1.z), splat2(bv1.w)};
#pragma unroll
            for (int i = 0; i < 4; i++)
#pragma unroll
                for (int j = 0; j < 8; j++) acc2[i][j] = ffma2(ap[i], bp[j], acc2[i][j]);
        }
    }

    // epilogue: rows ty*8 + 2*i2 (+1), cols bn*128 + tx*8 + j
    const int ncol = bn * 128 + tx * 8;
    float bb[8];
#pragma unroll
    for (int j = 0; j < 8; j++) bb[j] = bias[ncol + j];
    float* Cb = g_gx + (size_t)(bm * 128 + ty * 8) * 2048 + ncol;
#pragma unroll
    for (int i2 = 0; i2 < 4; i2++) {
        float r0[8], r1[8];
#pragma unroll
        for (int j = 0; j < 8; j++) {
            float2 v = unpack2(acc2[i2][j]);
            r0[j] = v.x + bb[j];
            r1[j] = v.y + bb[j];
        }
        float* p0 = Cb + (size_t)(2 * i2) * 2048;
        float* p1 = p0 + 2048;
        *(float4*)(p0)     = make_float4(r0[0], r0[1], r0[2], r0[3]);
        *(float4*)(p0 + 4) = make_float4(r0[4], r0[5], r0[6], r0[7]);
        *(float4*)(p1)     = make_float4(r1[0], r1[1], r1[2], r1[3]);
        *(float4*)(p1 + 4) = make_float4(r1[4], r1[5], r1[6], r1[7]);
    }
}

// ------------------------- persistent recurrence -------------------------
// 128 blocks x 128 threads. Block bi owns hidden units n0=4*bi..+3 (16 gate rows).
// Shared: wTs/hTs k-pair-interleaved [256][RS] so f32x2 packs along K with no splats.
__global__ __launch_bounds__(128) void lstm_rec(const float* __restrict__ w_hh,
                                                const float* __restrict__ b_hh,
                                                const float* __restrict__ c0,
                                                float* __restrict__ hfin, int storeSeq) {
    extern __shared__ float smem[];
    float* wTs  = smem;             // 256*RS = 9216
    float* hTs  = smem + 9216;      // 9216
    float* red  = smem + 18432;     // [4][16][16] = 1024
    float* gbuf = smem + 19456;     // [16][16]    = 256
    float* bsm  = smem + 19712;     // [16]

    const int tid = threadIdx.x;
    const int bi = blockIdx.x;
    const int n0 = bi * 4;

    // preload w_hh slice: rows r = gi*4+ui  ->  wTs[k2][r*2 + (k&1)]
    for (int idx = tid; idx < 16 * 512; idx += 128) {
        int r = idx >> 9, k = idx & 511;
        int gi = r >> 2, ui = r & 3;
        wTs[(k >> 1) * RS + r * 2 + (k & 1)] = w_hh[(size_t)(gi * HID + n0 + ui) * HID + k];
    }
    if (tid < 16) { int gi = tid >> 2, ui = tid & 3; bsm[tid] = b_hh[gi * HID + n0 + ui]; }

    float c = 0.f;
    if (tid < 64) { int u = tid >> 4, b = tid & 15; c = c0[b * HID + n0 + u]; }

    const int lane = tid & 31, wid = tid >> 5;
    const int ks = lane & 1, bg = (lane >> 1) & 3, rg = lane >> 3;
    const int r0 = tid >> 4;   // 0..7
    const int b0 = tid & 15;
    const int r1 = r0 + 8;     // 8..15
    const int gr0 = (r0 >> 2) * HID + n0 + (r0 & 3);
    const int gr1 = (r1 >> 2) * HID + n0 + (r1 & 3);
    const float* wbase = wTs + (wid * 64 + ks) * RS + rg * 8;
    const float* hbase = hTs + (wid * 64 + ks) * RS + bg * 8;

    __syncthreads();

    for (int t = 0; t < T_STEPS; t++) {
        if (t > 0) {
            // grid barrier: all blocks finished step t-1 (h writes published)
            __syncthreads();
            if (tid == 0) {
                __threadfence();
                unsigned tk = atomicAdd(&g_arrive, 1u);
                if (tk == (unsigned)t * NBLK - 1u) {
                    *(volatile unsigned*)&g_release = (unsigned)t;
                } else {
                    while (*(volatile unsigned*)&g_release < (unsigned)t) {}
                }
                __threadfence();
            }
            __syncthreads();
        }
        const int par = t & 1;

        // stage h (bypass L1: written by other SMs) and prefetch gx for this step
        const float4* hsrc = (const float4*)&g_hT[par][0][0];
#pragma unroll
        for (int it = 0; it < 16; it++) {
            int idx = tid + it * 128;
            float4 v = __ldcg(hsrc + idx);
            int k2 = idx >> 3, c4 = idx & 7;
            *(float4*)&hTs[k2 * RS + c4 * 4] = v;
        }
        float gx0 = __ldg(&g_gx[((size_t)b0 * T_STEPS + t) * 2048 + gr0]);
        float gx1 = __ldg(&g_gx[((size_t)b0 * T_STEPS + t) * 2048 + gr1]);
        __syncthreads();

        // 16 gate-rows x 16 batches, K=512, f32x2 packed along K
        ull acc2[4][4];
#pragma unroll
        for (int i = 0; i < 4; i++)
#pragma unroll
            for (int j = 0; j < 4; j++) acc2[i][j] = 0ull;

#pragma unroll 8
        for (int j = 0; j < 32; j++) {
            const float* wp = wbase + j * (2 * RS);
            const float* hp = hbase + j * (2 * RS);
            ulonglong2 wv0 = *(const ulonglong2*)wp;
            ulonglong2 wv1 = *(const ulonglong2*)(wp + 4);
            ulonglong2 hv0 = *(const ulonglong2*)hp;
            ulonglong2 hv1 = *(const ulonglong2*)(hp + 4);
            ull wr[4] = {wv0.x, wv0.y, wv1.x, wv1.y};
            ull hb[4] = {hv0.x, hv0.y, hv1.x, hv1.y};
#pragma unroll
            for (int i = 0; i < 4; i++)
#pragma unroll
                for (int j2 = 0; j2 < 4; j2++) acc2[i][j2] = ffma2(wr[i], hb[j2], acc2[i][j2]);
        }

        float accf[4][4];
#pragma unroll
        for (int i = 0; i < 4; i++)
#pragma unroll
            for (int j2 = 0; j2 < 4; j2++) {
                float2 v = unpack2(acc2[i][j2]);
                accf[i][j2] = v.x + v.y;
            }
#pragma unroll
        for (int i = 0; i < 4; i++)
#pragma unroll
            for (int j2 = 0; j2 < 4; j2++)
                accf[i][j2] += __shfl_xor_sync(0xffffffffu, accf[i][j2], 1);

        if (ks == 0) {
#pragma unroll
            for (int i = 0; i < 4; i++)
                *(float4*)&red[(wid * 16 + rg * 4 + i) * 16 + bg * 4] =
                    make_float4(accf[i][0], accf[i][1], accf[i][2], accf[i][3]);
        }
        __syncthreads();

        // combine partials + gx + bias, apply activations
        {
            float s0 = red[r0 * 16 + b0] + red[256 + r0 * 16 + b0] + red[512 + r0 * 16 + b0] +
                       red[768 + r0 * 16 + b0] + gx0 + bsm[r0];
            float s1 = red[r1 * 16 + b0] + red[256 + r1 * 16 + b0] + red[512 + r1 * 16 + b0] +
                       red[768 + r1 * 16 + b0] + gx1 + bsm[r1];
            float a0 = sigm(s0);                              // rows 0..7: i, f gates
            float a1 = (r1 < 12) ? tanhf(s1) : sigm(s1);      // rows 8..11: g (tanh), 12..15: o
            gbuf[r0 * 16 + b0] = a0;
            gbuf[r1 * 16 + b0] = a1;
        }
        __syncthreads();

        if (tid < 64) {
            int u = tid >> 4, b = tid & 15;
            float iv = gbuf[(0 + u) * 16 + b];
            float fv = gbuf[(4 + u) * 16 + b];
            float gv = gbuf[(8 + u) * 16 + b];
            float ov = gbuf[(12 + u) * 16 + b];
            c = fv * c + iv * gv;
            float h = ov * tanhf(c);
            int n = n0 + u;
            g_hT[par ^ 1][n >> 1][b * 2 + (n & 1)] = h;
            if (storeSeq) g_seq[((size_t)b * T_STEPS + t) * HID + n] = h;
            if (t == T_STEPS - 1) hfin[b * HID + n] = h;
        }
    }
}

// ------------------------- launch -------------------------
extern "C" void kernel_launch(void* const* d_in, const int* in_sizes, int n_in,
                              void* d_out, int out_size) {
    const float* x     = (const float*)d_in[0];
    const float* h0    = (const float*)d_in[1];
    const float* c0    = (const float*)d_in[2];
    const float* w_ih0 = (const float*)d_in[3];
    const float* w_hh0 = (const float*)d_in[4];
    const float* b_ih0 = (const float*)d_in[5];
    const float* b_hh0 = (const float*)d_in[6];
    const float* w_ih1 = (const float*)d_in[7];
    const float* w_hh1 = (const float*)d_in[8];
    const float* b_ih1 = (const float*)d_in[9];
    const float* b_hh1 = (const float*)d_in[10];
    float* out = (float*)d_out;

    const int rec_smem = 19728 * 4;  // 78,912 B
    cudaFuncSetAttribute(lstm_rec, cudaFuncAttributeMaxDynamicSharedMemorySize, rec_smem);

    dim3 ggrid(16, 128);  // N-tiles x M-tiles

    // layer 0
    init_state<<<32, 256>>>(h0);
    gemm_gates<<<ggrid, 256>>>(x, 0, w_ih0, b_ih0);
    lstm_rec<<<NBLK, 128, rec_smem>>>(w_hh0, b_hh0, c0, out, 1);

    // layer 1
    init_state<<<32, 256>>>(h0 + BATCH * HID);
    gemm_gates<<<ggrid, 256>>>(nullptr, 1, w_ih1, b_ih1);
    lstm_rec<<<NBLK, 128, rec_smem>>>(w_hh1, b_hh1, c0 + BATCH * HID, out + BATCH * HID, 0);
}